// round 1
// baseline (speedup 1.0000x reference)
#include <cuda_runtime.h>

#define D_MODEL 1024
#define N_EXP   16
#define MAX_B   32768
#define THRESH  0.3f

// ---------------- device-global scratch (no allocation allowed) ----------------
__device__ int   g_counts[N_EXP];
__device__ int   g_offsets[N_EXP];
__device__ int   g_tile[MAX_B];
__device__ int   g_rank[MAX_B];
__device__ int   g_perm[MAX_B];
__device__ float g_qsig[N_EXP * D_MODEL];

// ---------------- tiny setup kernels ----------------
__global__ void zero_counts_kernel() {
    if (threadIdx.x < N_EXP) g_counts[threadIdx.x] = 0;
}

__global__ void quantize_sig_kernel(const float* __restrict__ sig) {
    int i = blockIdx.x * blockDim.x + threadIdx.x;
    if (i < N_EXP * D_MODEL) {
        float s = sig[i];
        g_qsig[i] = (s > THRESH) ? 1.0f : ((s < -THRESH) ? -1.0f : 0.0f);
    }
}

// ---------------- router: one warp per row ----------------
// scores[b,e] = sum_k x[b,k] * qsig[e,k]; argmax (first max wins, matches jnp.argmax)
__global__ void router_kernel(const float* __restrict__ x, int B) {
    int tid  = threadIdx.x;
    int warp = tid >> 5;
    int lane = tid & 31;
    int row  = blockIdx.x * 8 + warp;
    if (row >= B) return;

    float acc[N_EXP];
#pragma unroll
    for (int e = 0; e < N_EXP; e++) acc[e] = 0.0f;

    const float4* xr = (const float4*)(x + (size_t)row * D_MODEL);
#pragma unroll 2
    for (int kk = lane; kk < D_MODEL / 4; kk += 32) {
        float4 xv = __ldg(&xr[kk]);
#pragma unroll
        for (int e = 0; e < N_EXP; e++) {
            float4 q = *(const float4*)(g_qsig + e * D_MODEL + kk * 4);
            acc[e] += xv.x * q.x + xv.y * q.y + xv.z * q.z + xv.w * q.w;
        }
    }
#pragma unroll
    for (int e = 0; e < N_EXP; e++) {
#pragma unroll
        for (int off = 16; off >= 1; off >>= 1)
            acc[e] += __shfl_xor_sync(0xffffffffu, acc[e], off);
    }
    if (lane == 0) {
        int best = 0;
        float bv = acc[0];
#pragma unroll
        for (int e = 1; e < N_EXP; e++)
            if (acc[e] > bv) { bv = acc[e]; best = e; }  // strict > : first max wins
        g_tile[row] = best;
        g_rank[row] = atomicAdd(&g_counts[best], 1);
    }
}

// ---------------- exclusive prefix over 16 counts ----------------
__global__ void offsets_kernel() {
    if (threadIdx.x == 0) {
        int s = 0;
#pragma unroll
        for (int e = 0; e < N_EXP; e++) { g_offsets[e] = s; s += g_counts[e]; }
    }
}

// ---------------- scatter rows into expert-sorted order ----------------
__global__ void scatter_kernel(int B, float* __restrict__ tail) {
    int row = blockIdx.x * blockDim.x + threadIdx.x;
    if (row >= B) return;
    int e = g_tile[row];
    g_perm[g_offsets[e] + g_rank[row]] = row;
    if (tail) tail[row] = (float)e;
}

// ---------------- per-expert GEMM 128x128 tile, BK=8, 8x8 micro-tile ----------------
// y[m,n] = relu( sum_k x[perm_m, k] * W[e, n, k] + b[e, n] ) + x[perm_m, n]
__global__ __launch_bounds__(256, 2) void expert_gemm_kernel(
    const float* __restrict__ x, const float* __restrict__ W,
    const float* __restrict__ bias, float* __restrict__ out, int B)
{
    const int e   = blockIdx.z;
    const int cnt = g_counts[e];
    const int m0  = blockIdx.y * 128;
    if (m0 >= cnt) return;                 // early-exit for empty tiles
    const int n0   = blockIdx.x * 128;
    const int base = g_offsets[e];

    __shared__ float As[8][128];
    __shared__ float Bs[8][128];

    const int t  = threadIdx.x;
    const int lm = t >> 1;                 // 0..127: tile row being loaded
    const int lk = (t & 1) * 4;            // 0 or 4: k quad

    int grA = -1;
    if (m0 + lm < cnt) grA = g_perm[base + m0 + lm];
    const float* aPtr = (grA >= 0) ? (x + (size_t)grA * D_MODEL + lk) : nullptr;
    const float* bPtr = W + ((size_t)e * D_MODEL + (size_t)(n0 + lm)) * D_MODEL + lk;

    const int tx = t & 15;
    const int ty = t >> 4;

    float acc[8][8];
#pragma unroll
    for (int i = 0; i < 8; i++)
#pragma unroll
        for (int j = 0; j < 8; j++) acc[i][j] = 0.0f;

    float4 av = aPtr ? *(const float4*)aPtr : make_float4(0.f, 0.f, 0.f, 0.f);
    float4 bv = *(const float4*)bPtr;

    for (int kt = 0; kt < D_MODEL / 8; kt++) {
        __syncthreads();
        As[lk + 0][lm] = av.x; As[lk + 1][lm] = av.y;
        As[lk + 2][lm] = av.z; As[lk + 3][lm] = av.w;
        Bs[lk + 0][lm] = bv.x; Bs[lk + 1][lm] = bv.y;
        Bs[lk + 2][lm] = bv.z; Bs[lk + 3][lm] = bv.w;
        __syncthreads();

        if (kt + 1 < D_MODEL / 8) {        // prefetch next k-slab while computing
            int koff = (kt + 1) * 8;
            av = aPtr ? *(const float4*)(aPtr + koff) : make_float4(0.f, 0.f, 0.f, 0.f);
            bv = *(const float4*)(bPtr + koff);
        }

#pragma unroll
        for (int k = 0; k < 8; k++) {
            float a[8], b[8];
            *(float4*)&a[0] = *(const float4*)&As[k][ty * 4];
            *(float4*)&a[4] = *(const float4*)&As[k][64 + ty * 4];
            *(float4*)&b[0] = *(const float4*)&Bs[k][tx * 4];
            *(float4*)&b[4] = *(const float4*)&Bs[k][64 + tx * 4];
#pragma unroll
            for (int i = 0; i < 8; i++)
#pragma unroll
                for (int j = 0; j < 8; j++)
                    acc[i][j] = fmaf(a[i], b[j], acc[i][j]);
        }
    }

    // fused epilogue: +bias, relu, +residual, scatter back to original row
#pragma unroll
    for (int i = 0; i < 8; i++) {
        int mr = m0 + ((i < 4) ? (ty * 4 + i) : (64 + ty * 4 + (i - 4)));
        if (mr >= cnt) continue;
        int gr = g_perm[base + mr];
        const float* xr   = x   + (size_t)gr * D_MODEL;
        float*       orow = out + (size_t)gr * D_MODEL;
#pragma unroll
        for (int j = 0; j < 8; j++) {
            int nc = n0 + ((j < 4) ? (tx * 4 + j) : (64 + tx * 4 + (j - 4)));
            float v = acc[i][j] + bias[e * D_MODEL + nc];
            v = fmaxf(v, 0.0f);
            orow[nc] = v + xr[nc];
        }
    }
}

// ---------------- launch ----------------
extern "C" void kernel_launch(void* const* d_in, const int* in_sizes, int n_in,
                              void* d_out, int out_size) {
    const float* x   = (const float*)d_in[0];
    const float* sig = (const float*)d_in[1];
    const float* W   = (const float*)d_in[2];
    const float* b   = (const float*)d_in[3];
    float* out = (float*)d_out;

    const int B = in_sizes[0] / D_MODEL;

    zero_counts_kernel<<<1, 32>>>();
    quantize_sig_kernel<<<(N_EXP * D_MODEL + 255) / 256, 256>>>(sig);
    router_kernel<<<(B + 7) / 8, 256>>>(x, B);
    offsets_kernel<<<1, 32>>>();

    // reference returns (out, tile_indices): write indices tail only if buffer has room
    float* tail = nullptr;
    if ((long long)out_size >= (long long)B * D_MODEL + B)
        tail = out + (size_t)B * D_MODEL;
    scatter_kernel<<<(B + 255) / 256, 256>>>(B, tail);

    dim3 grid(D_MODEL / 128, (B + 127) / 128, N_EXP);
    expert_gemm_kernel<<<grid, 256>>>(x, W, b, out, B);
}

// round 3
// speedup vs baseline: 2.0255x; 2.0255x over previous
#include <cuda_runtime.h>
#include <cstdint>

#define D_MODEL 1024
#define N_EXP   16
#define MAX_B   32768
#define THRESH  0.3f

// ---- GEMM tiling ----
#define BM 128
#define BN 128
#define BK 32
#define KPAD 36                         // 32 + 4 pad floats -> conflict-free frag LDS
#define STG_A_BYTES (BM * KPAD * 4)     // 18432
#define STG_BYTES   (2 * BM * KPAD * 4) // 36864 (A + B)
#define NCH (D_MODEL / BK)              // 32 k-chunks
#define SMEM_TOTAL (2 * STG_BYTES)      // 73728 double-buffered

// ---------------- device-global scratch ----------------
__device__ int   g_counts[N_EXP];
__device__ int   g_offsets[N_EXP];
__device__ int   g_tile[MAX_B];
__device__ int   g_rank[MAX_B];
__device__ int   g_perm[MAX_B];
__device__ float g_qsig[N_EXP * D_MODEL];

// ---------------- PTX helpers ----------------
__device__ __forceinline__ uint32_t smem_u32(const void* p) {
    uint32_t a;
    asm("{ .reg .u64 t; cvta.to.shared.u64 t, %1; cvt.u32.u64 %0, t; }" : "=r"(a) : "l"(p));
    return a;
}
__device__ __forceinline__ void cpa16(uint32_t dst, const void* src) {
    asm volatile("cp.async.cg.shared.global [%0], [%1], 16;" :: "r"(dst), "l"(src));
}
#define CP_COMMIT() asm volatile("cp.async.commit_group;" ::: "memory")

__device__ __forceinline__ uint32_t f2tf(float f) {
    uint32_t r;
    asm("cvt.rna.tf32.f32 %0, %1;" : "=r"(r) : "f"(f));
    return r;
}
__device__ __forceinline__ void mma_tf32(float* c, const uint32_t* a, const uint32_t* b) {
    asm volatile(
        "mma.sync.aligned.m16n8k8.row.col.f32.tf32.tf32.f32 "
        "{%0,%1,%2,%3}, {%4,%5,%6,%7}, {%8,%9}, {%0,%1,%2,%3};"
        : "+f"(c[0]), "+f"(c[1]), "+f"(c[2]), "+f"(c[3])
        : "r"(a[0]), "r"(a[1]), "r"(a[2]), "r"(a[3]), "r"(b[0]), "r"(b[1]));
}

// ---------------- tiny setup kernels ----------------
__global__ void zero_counts_kernel() {
    if (threadIdx.x < N_EXP) g_counts[threadIdx.x] = 0;
}

__global__ void quantize_sig_kernel(const float* __restrict__ sig) {
    int i = blockIdx.x * blockDim.x + threadIdx.x;
    if (i < N_EXP * D_MODEL) {
        float s = sig[i];
        g_qsig[i] = (s > THRESH) ? 1.0f : ((s < -THRESH) ? -1.0f : 0.0f);
    }
}

// ---------------- router: one warp per row ----------------
__global__ void router_kernel(const float* __restrict__ x, int B) {
    int tid  = threadIdx.x;
    int warp = tid >> 5;
    int lane = tid & 31;
    int row  = blockIdx.x * 8 + warp;
    if (row >= B) return;

    float acc[N_EXP];
#pragma unroll
    for (int e = 0; e < N_EXP; e++) acc[e] = 0.0f;

    const float4* xr = (const float4*)(x + (size_t)row * D_MODEL);
#pragma unroll 2
    for (int kk = lane; kk < D_MODEL / 4; kk += 32) {
        float4 xv = __ldg(&xr[kk]);
#pragma unroll
        for (int e = 0; e < N_EXP; e++) {
            float4 q = *(const float4*)(g_qsig + e * D_MODEL + kk * 4);
            acc[e] += xv.x * q.x + xv.y * q.y + xv.z * q.z + xv.w * q.w;
        }
    }
#pragma unroll
    for (int e = 0; e < N_EXP; e++) {
#pragma unroll
        for (int off = 16; off >= 1; off >>= 1)
            acc[e] += __shfl_xor_sync(0xffffffffu, acc[e], off);
    }
    if (lane == 0) {
        int best = 0;
        float bv = acc[0];
#pragma unroll
        for (int e = 1; e < N_EXP; e++)
            if (acc[e] > bv) { bv = acc[e]; best = e; }  // strict > : first max wins
        g_tile[row] = best;
        g_rank[row] = atomicAdd(&g_counts[best], 1);
    }
}

__global__ void offsets_kernel() {
    if (threadIdx.x == 0) {
        int s = 0;
#pragma unroll
        for (int e = 0; e < N_EXP; e++) { g_offsets[e] = s; s += g_counts[e]; }
    }
}

__global__ void scatter_kernel(int B, float* __restrict__ tail) {
    int row = blockIdx.x * blockDim.x + threadIdx.x;
    if (row >= B) return;
    int e = g_tile[row];
    g_perm[g_offsets[e] + g_rank[row]] = row;
    if (tail) tail[row] = (float)e;
}

// ---------------- tf32 mma.sync expert GEMM ----------------
// CTA: 128 gathered rows x 128 cols x K=1024. 8 warps 2x4, warp tile 64x32.
// y[m,n] = relu( sum_k x[perm_m,k] * W[e,n,k] + b[e,n] ) + x[perm_m,n]
__global__ void __launch_bounds__(256, 2) expert_gemm_mma(
    const float* __restrict__ x, const float* __restrict__ W,
    const float* __restrict__ bias, float* __restrict__ out, int B)
{
    const int e   = blockIdx.z;
    const int cnt = g_counts[e];
    const int m0  = blockIdx.y * BM;
    if (m0 >= cnt) return;                 // empty tile
    const int n0   = blockIdx.x * BN;
    const int base = g_offsets[e];
    const int rem  = cnt - m0;

    extern __shared__ char smem[];
    const uint32_t sb = smem_u32(smem);

    const int tid  = threadIdx.x;
    const int wid  = tid >> 5;
    const int lane = tid & 31;
    const int g    = lane >> 2;            // 0..7
    const int t    = lane & 3;             // 0..3
    const int warp_m = wid >> 2;           // 0..1 (64-row halves)
    const int warp_n = wid & 3;            // 0..3 (32-col quarters)

    // ---- async loader mapping: thread -> (row, 64B half-row) ----
    const int lrow = tid >> 1;             // 0..127
    const int lsegB = (tid & 1) * 64;      // byte offset 0 or 64 within the 128B k-chunk row
    const int arloc = (lrow < rem) ? lrow : (rem - 1);
    const char* aSrc = (const char*)(x + (size_t)__ldg(&g_perm[base + m0 + arloc]) * D_MODEL) + lsegB;
    const char* bSrc = (const char*)(W + ((size_t)e * D_MODEL + (size_t)(n0 + lrow)) * D_MODEL) + lsegB;
    const uint32_t aDst = sb + (uint32_t)lrow * (KPAD * 4) + lsegB;
    const uint32_t bDst = aDst + STG_A_BYTES;

    // prologue: stage 0
#pragma unroll
    for (int s = 0; s < 4; s++) {
        cpa16(aDst + s * 16, aSrc + s * 16);
        cpa16(bDst + s * 16, bSrc + s * 16);
    }
    CP_COMMIT();

    float acc[4][4][4];
#pragma unroll
    for (int i = 0; i < 4; i++)
#pragma unroll
        for (int j = 0; j < 4; j++)
#pragma unroll
            for (int r = 0; r < 4; r++) acc[i][j][r] = 0.0f;

    for (int c = 0; c < NCH; c++) {
        const int cur = c & 1;
        if (c + 1 < NCH) {
            const uint32_t nb = (c + 1) & 1;
            const char* a = aSrc + (size_t)(c + 1) * 128;
            const char* b = bSrc + (size_t)(c + 1) * 128;
#pragma unroll
            for (int s = 0; s < 4; s++) {
                cpa16(aDst + nb * STG_BYTES + s * 16, a + s * 16);
                cpa16(bDst + nb * STG_BYTES + s * 16, b + s * 16);
            }
            CP_COMMIT();
            asm volatile("cp.async.wait_group 1;" ::: "memory");
        } else {
            asm volatile("cp.async.wait_group 0;" ::: "memory");
        }
        __syncthreads();

        const float* sA = (const float*)(smem + cur * STG_BYTES) + warp_m * 64 * KPAD;
        const float* sB = (const float*)(smem + cur * STG_BYTES + STG_A_BYTES) + warp_n * 32 * KPAD;

#pragma unroll
        for (int k0 = 0; k0 < BK; k0 += 8) {
            uint32_t af[4][4], bf[4][2];
#pragma unroll
            for (int mf = 0; mf < 4; mf++) {
                const float* pr = sA + (mf * 16 + g) * KPAD + k0 + t;
                af[mf][0] = f2tf(pr[0]);
                af[mf][1] = f2tf(pr[8 * KPAD]);
                af[mf][2] = f2tf(pr[4]);
                af[mf][3] = f2tf(pr[8 * KPAD + 4]);
            }
#pragma unroll
            for (int nf = 0; nf < 4; nf++) {
                const float* pc = sB + (nf * 8 + g) * KPAD + k0 + t;
                bf[nf][0] = f2tf(pc[0]);
                bf[nf][1] = f2tf(pc[4]);
            }
#pragma unroll
            for (int mf = 0; mf < 4; mf++)
#pragma unroll
                for (int nf = 0; nf < 4; nf++)
                    mma_tf32(acc[mf][nf], af[mf], bf[nf]);
        }
        __syncthreads();
    }

    // ---- fused epilogue: +bias, relu, +residual, scatter to original rows ----
    const float* bias_e = bias + e * D_MODEL;
#pragma unroll
    for (int mf = 0; mf < 4; mf++) {
#pragma unroll
        for (int h = 0; h < 2; h++) {
            const int rloc = warp_m * 64 + mf * 16 + g + h * 8;
            if (rloc >= rem) continue;
            const int gr = __ldg(&g_perm[base + m0 + rloc]);
            const float* xr   = x   + (size_t)gr * D_MODEL;
            float*       orow = out + (size_t)gr * D_MODEL;
#pragma unroll
            for (int nf = 0; nf < 4; nf++) {
                const int col = n0 + warp_n * 32 + nf * 8 + t * 2;
                const float2 bb = *(const float2*)(bias_e + col);
                const float2 xx = __ldg((const float2*)(xr + col));
                float v0 = fmaxf(acc[mf][nf][h * 2 + 0] + bb.x, 0.0f) + xx.x;
                float v1 = fmaxf(acc[mf][nf][h * 2 + 1] + bb.y, 0.0f) + xx.y;
                *(float2*)(orow + col) = make_float2(v0, v1);
            }
        }
    }
}

// ---------------- launch ----------------
extern "C" void kernel_launch(void* const* d_in, const int* in_sizes, int n_in,
                              void* d_out, int out_size) {
    const float* x   = (const float*)d_in[0];
    const float* sig = (const float*)d_in[1];
    const float* W   = (const float*)d_in[2];
    const float* b   = (const float*)d_in[3];
    float* out = (float*)d_out;

    const int B = in_sizes[0] / D_MODEL;

    cudaFuncSetAttribute(expert_gemm_mma,
                         cudaFuncAttributeMaxDynamicSharedMemorySize, SMEM_TOTAL);

    zero_counts_kernel<<<1, 32>>>();
    quantize_sig_kernel<<<(N_EXP * D_MODEL + 255) / 256, 256>>>(sig);
    router_kernel<<<(B + 7) / 8, 256>>>(x, B);
    offsets_kernel<<<1, 32>>>();

    float* tail = nullptr;
    if ((long long)out_size >= (long long)B * D_MODEL + B)
        tail = out + (size_t)B * D_MODEL;
    scatter_kernel<<<(B + 255) / 256, 256>>>(B, tail);

    dim3 grid(D_MODEL / BN, (B + BM - 1) / BM, N_EXP);
    expert_gemm_mma<<<grid, 256, SMEM_TOTAL>>>(x, W, b, out, B);
}